// round 8
// baseline (speedup 1.0000x reference)
#include <cuda_runtime.h>

#define BB 32
#define LL 200
#define KK 200
#define CC 50
#define OUTC 250
#define EPSF 1e-6f

// ---------------- device scratch (static allocations are allowed) ----------
__device__ float g_inv_qn[BB*LL];
__device__ float g_inv_dn[BB*LL];
__device__ float g_inv_mqn[BB*LL*CC];   // q under maxpool_M
__device__ float g_inv_mpn[BB*LL*CC];   // d under maxpool_M
__device__ float g_inv_fpn[BB*LL*CC];   // d under full_M
__device__ float g_inv_apn[BB*LL*CC];   // d under att_M
__device__ float g_inv_xpn[BB*LL*CC];   // d under max_att_M
__device__ float g_inv_xqn[BB*LL*CC];   // q under max_att_M
__device__ float g_inv_fqn[BB*CC];      // q_last under full_M
__device__ float g_fullM2T[KK*CC];
__device__ float g_attM2T[KK*CC];
__device__ float g_xattM2T[KK*CC];
__device__ float g_mpM2T[KK*CC];
__device__ float g_mpM2[CC*KK];

// ---------------- kernel 0: squared / transposed perspective matrices ------
__global__ void k_prep(const float* __restrict__ fullM, const float* __restrict__ mpM,
                       const float* __restrict__ attM,  const float* __restrict__ xattM)
{
    int idx = blockIdx.x * 256 + threadIdx.x;
    if (idx >= CC*KK) return;
    int c = idx / KK, k = idx - c*KK;
    float fm = fullM[idx];  g_fullM2T[k*CC + c] = fm*fm;
    float am = attM[idx];   g_attM2T [k*CC + c] = am*am;
    float xm = xattM[idx];  g_xattM2T[k*CC + c] = xm*xm;
    float mm = mpM[idx];    g_mpM2T  [k*CC + c] = mm*mm;
    g_mpM2[idx] = mm*mm;
}

// ---------------- kernel 1: all per-row inverse norms ----------------------
__global__ void __launch_bounds__(512) k_norms(const float* __restrict__ q_rep,
                                               const float* __restrict__ d_rep)
{
    __shared__ float qr[KK], dr[KK];
    int row = blockIdx.x;                 // b*LL + l
    int tid = threadIdx.x;
    if (tid < KK){ qr[tid] = q_rep[(size_t)row*KK + tid];
                   dr[tid] = d_rep[(size_t)row*KK + tid]; }
    __syncthreads();

    int grp = tid >> 6, c = tid & 63;
    if (grp < 6){
        if (c < CC){
            const float* rv; const float* M2T; float* outp;
            switch (grp){
                case 0:  rv = qr; M2T = g_mpM2T;   outp = g_inv_mqn; break;
                case 1:  rv = qr; M2T = g_xattM2T; outp = g_inv_xqn; break;
                case 2:  rv = dr; M2T = g_mpM2T;   outp = g_inv_mpn; break;
                case 3:  rv = dr; M2T = g_fullM2T; outp = g_inv_fpn; break;
                case 4:  rv = dr; M2T = g_attM2T;  outp = g_inv_apn; break;
                default: rv = dr; M2T = g_xattM2T; outp = g_inv_xpn; break;
            }
            float s = 0.f;
            #pragma unroll 4
            for (int k = 0; k < KK; k++){ float v = rv[k]; s += v*v*M2T[k*CC + c]; }
            outp[(size_t)row*CC + c] = 1.0f / sqrtf(fmaxf(s, EPSF));
        }
    } else if (grp == 6){
        int lane = tid & 31;
        float s = 0.f;
        for (int k = lane; k < KK; k += 32){ float v = qr[k]; s += v*v; }
        #pragma unroll
        for (int off = 16; off; off >>= 1) s += __shfl_xor_sync(0xffffffffu, s, off);
        if (lane == 0) g_inv_qn[row] = 1.0f / sqrtf(fmaxf(s, EPSF));
    } else {
        int lane = tid & 31;
        float s = 0.f;
        for (int k = lane; k < KK; k += 32){ float v = dr[k]; s += v*v; }
        #pragma unroll
        for (int off = 16; off; off >>= 1) s += __shfl_xor_sync(0xffffffffu, s, off);
        if (lane == 0) g_inv_dn[row] = 1.0f / sqrtf(fmaxf(s, EPSF));
    }
}

// ---------------- kernel 2: q_last norms under full_M ----------------------
__global__ void k_fqn(const float* __restrict__ q_last)
{
    __shared__ float ql[KK];
    int b = blockIdx.x;
    for (int k = threadIdx.x; k < KK; k += 64) ql[k] = q_last[(size_t)b*KK + k];
    __syncthreads();
    int c = threadIdx.x;
    if (c >= CC) return;
    float s = 0.f;
    for (int k = 0; k < KK; k++){ float v = ql[k]; s += v*v*g_fullM2T[k*CC + c]; }
    g_inv_fqn[b*CC + c] = 1.0f / sqrtf(fmaxf(s, EPSF));
}

// ---------------- kernel 3: rel / wq / full / att / max-att ----------------
// one block per (b, 8-row d tile); rel stays in shared memory
__global__ void __launch_bounds__(256) k_relmatch(
    const float* __restrict__ q_rep, const float* __restrict__ q_last,
    const float* __restrict__ q_mask, const float* __restrict__ d_rep,
    const float* __restrict__ d_mask, float* __restrict__ out)
{
    __shared__ float dsm[8][KK];
    __shared__ float relsm[8][LL];
    __shared__ float wqsm[8][KK];
    __shared__ float mqsm[8][KK];
    __shared__ float qlsm[KK];
    __shared__ float invrelsum[8];
    __shared__ int   bestj[8];

    int blk = blockIdx.x;
    int b   = blk / (LL/8);
    int it  = blk - b*(LL/8);
    int i0  = it * 8;
    int row0 = b*LL + i0;
    int tid = threadIdx.x;

    for (int idx = tid; idx < 8*KK; idx += 256){
        int i = idx / KK, k = idx - i*KK;
        dsm[i][k] = d_rep[((size_t)row0 + i)*KK + k];
    }
    if (tid < KK) qlsm[tid] = q_last[(size_t)b*KK + tid];
    __syncthreads();

    int w = tid >> 5, lane = tid & 31;
    const float* qb = q_rep + (size_t)b*LL*KK;
    {
        int i = w;                        // warp w owns d-row i
        float invdn = g_inv_dn[row0 + i];
        float dm    = d_mask[row0 + i];
        for (int j = 0; j < LL; j++){
            float p = 0.f;
            for (int k = lane; k < KK; k += 32) p += dsm[i][k] * qb[(size_t)j*KK + k];
            #pragma unroll
            for (int off = 16; off; off >>= 1) p += __shfl_xor_sync(0xffffffffu, p, off);
            if (lane == 0)
                relsm[i][j] = p * g_inv_qn[b*LL + j] * invdn * q_mask[b*LL + j] * dm;
        }
        __syncwarp();
        // sum + first-occurrence argmax over j
        float s = 0.f, bv = -3.402823466e38f; int bi = 0;
        for (int j = lane; j < LL; j += 32){
            float v = relsm[i][j]; s += v;
            if (v > bv){ bv = v; bi = j; }
        }
        #pragma unroll
        for (int off = 16; off; off >>= 1){
            s += __shfl_xor_sync(0xffffffffu, s, off);
            float ov = __shfl_xor_sync(0xffffffffu, bv, off);
            int   oi = __shfl_xor_sync(0xffffffffu, bi, off);
            if (ov > bv || (ov == bv && oi < bi)){ bv = ov; bi = oi; }
        }
        if (lane == 0){ invrelsum[i] = 1.0f / (s + EPSF); bestj[i] = bi; }
        // gather best-matching q row (bi converged on all lanes)
        for (int k = lane; k < KK; k += 32) mqsm[i][k] = qb[(size_t)bi*KK + k];
    }
    __syncthreads();

    // wq[i][k] = (sum_j rel[i][j]*q[j][k]) * invrelsum[i]   (coalesced over k)
    if (tid < KK){
        int k = tid;
        float acc[8] = {0,0,0,0,0,0,0,0};
        for (int j = 0; j < LL; j++){
            float qv = qb[(size_t)j*KK + k];
            #pragma unroll
            for (int i = 0; i < 8; i++) acc[i] += relsm[i][j] * qv;
        }
        #pragma unroll
        for (int i = 0; i < 8; i++) wqsm[i][k] = acc[i] * invrelsum[i];
    }
    __syncthreads();

    // outputs: grp0 = full [0:50), grp1 = att [150:200), grp2 = max-att [200:250)
    int grp = tid >> 6, c = tid & 63;
    if (grp < 3 && c < CC){
        for (int i = 0; i < 8; i++){
            int row = row0 + i;
            if (grp == 0){
                float s = 0.f;
                #pragma unroll 4
                for (int k = 0; k < KK; k++) s += dsm[i][k]*qlsm[k]*g_fullM2T[k*CC + c];
                out[(size_t)row*OUTC + c] = s * g_inv_fpn[(size_t)row*CC + c] * g_inv_fqn[b*CC + c];
            } else if (grp == 1){
                float sn = 0.f, sq = 0.f;
                #pragma unroll 4
                for (int k = 0; k < KK; k++){
                    float m2 = g_attM2T[k*CC + c];
                    float wv = wqsm[i][k];
                    sn += dsm[i][k]*wv*m2;
                    sq += wv*wv*m2;
                }
                out[(size_t)row*OUTC + 150 + c] =
                    sn * g_inv_apn[(size_t)row*CC + c] * (1.0f / sqrtf(fmaxf(sq, EPSF)));
            } else {
                float s = 0.f;
                #pragma unroll 4
                for (int k = 0; k < KK; k++) s += dsm[i][k]*mqsm[i][k]*g_xattM2T[k*CC + c];
                out[(size_t)row*OUTC + 200 + c] = s * g_inv_xpn[(size_t)row*CC + c]
                                                    * g_inv_xqn[(size_t)(b*LL + bestj[i])*CC + c];
            }
        }
    }
}

// ---------------- kernel 4: maxpool matching (the 12.8 G-MAC term) ---------
// block = (b, c). A[i][k] = d*M2[c]*inv_mpn staged in smem (XOR-swizzled),
// q chunks pre-scaled by inv_mqn. Per-thread tile 8i x 5j; max/mean over j
// reduced via 8-lane shuffle groups, carried in registers across chunks.
#define JC 40
#define TJ 5
#define ASTRIDE 208                       // floats per A row (52 float4)
#define QSTRIDE 204                       // floats per q row (51 float4)
#define A_FLOATS (LL*ASTRIDE)             // 41600
#define Q_FLOATS (JC*QSTRIDE)             // 8160
#define MP_SMEM ((A_FLOATS + Q_FLOATS)*4) // 199040 bytes

__global__ void __launch_bounds__(224, 1) k_maxpool(const float* __restrict__ q_rep,
                                                    const float* __restrict__ d_rep,
                                                    float* __restrict__ out)
{
    extern __shared__ float sm[];
    float* Asm = sm;
    float* qsm = sm + A_FLOATS;
    int b = blockIdx.x / CC;
    int c = blockIdx.x - b*CC;
    int tid = threadIdx.x;

    // build A with swizzle: float4 slot (k4 ^ ((i>>3)&3)) within each row
    const float* drow = d_rep + (size_t)b*LL*KK;
    const float* m2   = g_mpM2 + (size_t)c*KK;
    for (int idx = tid; idx < LL*KK; idx += 224){
        int i = idx / KK, k = idx - i*KK;
        int phys = i*ASTRIDE + ((((k >> 2) ^ ((i >> 3) & 3)) << 2) | (k & 3));
        Asm[phys] = drow[idx] * m2[k] * g_inv_mpn[(size_t)(b*LL + i)*CC + c];
    }

    int ig = tid >> 3;                    // 0..27 (25 active)
    int jg = tid & 7;
    int igx = ig & 3;
    bool act = (ig < 25);
    unsigned mask = __ballot_sync(0xffffffffu, act);

    float rmax[8], rsum[8];
    #pragma unroll
    for (int r = 0; r < 8; r++){ rmax[r] = -3.402823466e38f; rsum[r] = 0.f; }

    const float4* Asm4 = (const float4*)Asm;
    const float4* qsm4 = (const float4*)qsm;
    int abase = ig*8*52;                  // float4 index of first owned A row
    int qbase = jg*TJ*51;                 // float4 index of first owned q row

    for (int j0 = 0; j0 < LL; j0 += JC){
        __syncthreads();                  // A build / previous-chunk reads done
        for (int idx = tid; idx < JC*KK; idx += 224){
            int j = idx / KK, k = idx - j*KK;
            qsm[j*QSTRIDE + k] = q_rep[((size_t)b*LL + j0 + j)*KK + k]
                               * g_inv_mqn[(size_t)(b*LL + j0 + j)*CC + c];
        }
        __syncthreads();

        if (act){
            float acc[8][TJ];
            #pragma unroll
            for (int r = 0; r < 8; r++)
                #pragma unroll
                for (int jj = 0; jj < TJ; jj++) acc[r][jj] = 0.f;

            #pragma unroll 2
            for (int k4 = 0; k4 < KK/4; k4++){
                float4 qv[TJ];
                #pragma unroll
                for (int jj = 0; jj < TJ; jj++) qv[jj] = qsm4[qbase + jj*51 + k4];
                int ak = k4 ^ igx;
                #pragma unroll
                for (int r = 0; r < 8; r++){
                    float4 av = Asm4[abase + r*52 + ak];
                    #pragma unroll
                    for (int jj = 0; jj < TJ; jj++){
                        acc[r][jj] += av.x * qv[jj].x;
                        acc[r][jj] += av.y * qv[jj].y;
                        acc[r][jj] += av.z * qv[jj].z;
                        acc[r][jj] += av.w * qv[jj].w;
                    }
                }
            }
            #pragma unroll
            for (int r = 0; r < 8; r++){
                float lmax = acc[r][0], lsum = acc[r][0];
                #pragma unroll
                for (int jj = 1; jj < TJ; jj++){
                    lmax = fmaxf(lmax, acc[r][jj]);
                    lsum += acc[r][jj];
                }
                #pragma unroll
                for (int off = 1; off < 8; off <<= 1){
                    lmax = fmaxf(lmax, __shfl_xor_sync(mask, lmax, off));
                    lsum += __shfl_xor_sync(mask, lsum, off);
                }
                rmax[r] = fmaxf(rmax[r], lmax);
                rsum[r] += lsum;
            }
        }
    }

    if (act && jg == 0){
        #pragma unroll
        for (int r = 0; r < 8; r++){
            int i = ig*8 + r;
            float* o = out + ((size_t)b*LL + i)*OUTC;
            o[ 50 + c] = rmax[r];
            o[100 + c] = rsum[r] * (1.0f/200.0f);
        }
    }
}

// ---------------- launcher -------------------------------------------------
extern "C" void kernel_launch(void* const* d_in, const int* in_sizes, int n_in,
                              void* d_out, int out_size)
{
    const float* q_rep  = (const float*)d_in[0];
    const float* q_last = (const float*)d_in[1];
    const float* q_mask = (const float*)d_in[2];
    const float* d_rep  = (const float*)d_in[3];
    // d_in[4] = d_last (unused by reference)
    const float* d_mask = (const float*)d_in[5];
    const float* fullM  = (const float*)d_in[6];
    const float* mpM    = (const float*)d_in[7];
    const float* attM   = (const float*)d_in[8];
    const float* xattM  = (const float*)d_in[9];
    float* out = (float*)d_out;

    k_prep<<<(CC*KK + 255)/256, 256>>>(fullM, mpM, attM, xattM);
    k_norms<<<BB*LL, 512>>>(q_rep, d_rep);
    k_fqn<<<BB, 64>>>(q_last);
    k_relmatch<<<BB*(LL/8), 256>>>(q_rep, q_last, q_mask, d_rep, d_mask, out);

    cudaFuncSetAttribute(k_maxpool, cudaFuncAttributeMaxDynamicSharedMemorySize, MP_SMEM);
    k_maxpool<<<BB*CC, 224, MP_SMEM>>>(q_rep, d_rep, out);
}

// round 10
// speedup vs baseline: 1.0821x; 1.0821x over previous
#include <cuda_runtime.h>

#define BB 32
#define LL 200
#define KK 200
#define CC 50
#define OUTC 250
#define EPSF 1e-6f

// ---------------- device scratch (static allocations are allowed) ----------
__device__ float g_inv_qn[BB*LL];
__device__ float g_inv_dn[BB*LL];
__device__ float g_inv_mqn[BB*LL*CC];   // q under maxpool_M
__device__ float g_inv_mpn[BB*LL*CC];   // d under maxpool_M
__device__ float g_inv_fpn[BB*LL*CC];   // d under full_M
__device__ float g_inv_apn[BB*LL*CC];   // d under att_M
__device__ float g_inv_xpn[BB*LL*CC];   // d under max_att_M
__device__ float g_inv_xqn[BB*LL*CC];   // q under max_att_M
__device__ float g_inv_fqn[BB*CC];      // q_last under full_M
__device__ float g_fullM2T[KK*CC];
__device__ float g_attM2T[KK*CC];
__device__ float g_xattM2T[KK*CC];
__device__ float g_mpM2T[KK*CC];
__device__ float g_mpM2[CC*KK];

// ---------------- kernel 0: squared / transposed perspective matrices ------
__global__ void k_prep(const float* __restrict__ fullM, const float* __restrict__ mpM,
                       const float* __restrict__ attM,  const float* __restrict__ xattM)
{
    int idx = blockIdx.x * 256 + threadIdx.x;
    if (idx >= CC*KK) return;
    int c = idx / KK, k = idx - c*KK;
    float fm = fullM[idx];  g_fullM2T[k*CC + c] = fm*fm;
    float am = attM[idx];   g_attM2T [k*CC + c] = am*am;
    float xm = xattM[idx];  g_xattM2T[k*CC + c] = xm*xm;
    float mm = mpM[idx];    g_mpM2T  [k*CC + c] = mm*mm;
    g_mpM2[idx] = mm*mm;
}

// ---------------- kernel 1: all per-row inverse norms ----------------------
__global__ void __launch_bounds__(512) k_norms(const float* __restrict__ q_rep,
                                               const float* __restrict__ d_rep)
{
    __shared__ float qr[KK], dr[KK];
    int row = blockIdx.x;                 // b*LL + l
    int tid = threadIdx.x;
    if (tid < KK){ qr[tid] = q_rep[(size_t)row*KK + tid];
                   dr[tid] = d_rep[(size_t)row*KK + tid]; }
    __syncthreads();

    int grp = tid >> 6, c = tid & 63;
    if (grp < 6){
        if (c < CC){
            const float* rv; const float* M2T; float* outp;
            switch (grp){
                case 0:  rv = qr; M2T = g_mpM2T;   outp = g_inv_mqn; break;
                case 1:  rv = qr; M2T = g_xattM2T; outp = g_inv_xqn; break;
                case 2:  rv = dr; M2T = g_mpM2T;   outp = g_inv_mpn; break;
                case 3:  rv = dr; M2T = g_fullM2T; outp = g_inv_fpn; break;
                case 4:  rv = dr; M2T = g_attM2T;  outp = g_inv_apn; break;
                default: rv = dr; M2T = g_xattM2T; outp = g_inv_xpn; break;
            }
            float s = 0.f;
            #pragma unroll 4
            for (int k = 0; k < KK; k++){ float v = rv[k]; s += v*v*M2T[k*CC + c]; }
            outp[(size_t)row*CC + c] = 1.0f / sqrtf(fmaxf(s, EPSF));
        }
    } else if (grp == 6){
        int lane = tid & 31;
        float s = 0.f;
        for (int k = lane; k < KK; k += 32){ float v = qr[k]; s += v*v; }
        #pragma unroll
        for (int off = 16; off; off >>= 1) s += __shfl_xor_sync(0xffffffffu, s, off);
        if (lane == 0) g_inv_qn[row] = 1.0f / sqrtf(fmaxf(s, EPSF));
    } else {
        int lane = tid & 31;
        float s = 0.f;
        for (int k = lane; k < KK; k += 32){ float v = dr[k]; s += v*v; }
        #pragma unroll
        for (int off = 16; off; off >>= 1) s += __shfl_xor_sync(0xffffffffu, s, off);
        if (lane == 0) g_inv_dn[row] = 1.0f / sqrtf(fmaxf(s, EPSF));
    }
}

// ---------------- kernel 2: q_last norms under full_M ----------------------
__global__ void k_fqn(const float* __restrict__ q_last)
{
    __shared__ float ql[KK];
    int b = blockIdx.x;
    for (int k = threadIdx.x; k < KK; k += 64) ql[k] = q_last[(size_t)b*KK + k];
    __syncthreads();
    int c = threadIdx.x;
    if (c >= CC) return;
    float s = 0.f;
    for (int k = 0; k < KK; k++){ float v = ql[k]; s += v*v*g_fullM2T[k*CC + c]; }
    g_inv_fqn[b*CC + c] = 1.0f / sqrtf(fmaxf(s, EPSF));
}

// ---------------- kernel 3: rel / wq / full / att / max-att (GEMM-style) ---
// block = (b, 25-row d tile). 256 blocks, 256 threads, ~97 KB dynamic smem.
// Phase 1: rel[25][200] via smem GEMM (q transposed in chunks, 5x5 thread tile)
// Phase 2: per-row sum + first-tie argmax (25 warp reductions total)
// Phase 3: wq = rel * q via coalesced float4 global loads (5i x 4k tile)
// Phase 4: 150 output columns per row, flattened over all threads.
#define RT 25                              // rows per tile
#define RKC 40                             // k-chunk for q transpose staging
#define DS_STR 204
#define REL_STR 208
#define WQ_STR 204
#define QS_STR 209                         // odd*... 209%32=17 -> conflict-free transpose
#define OFF_DSM   0
#define OFF_REL   (OFF_DSM + RT*DS_STR)          // 5100
#define OFF_WQ    (OFF_REL + RT*REL_STR)         // 10300
#define OFF_QSM   (OFF_WQ  + RT*WQ_STR)          // 15400
#define OFF_QSC   (OFF_QSM + RKC*QS_STR)         // 23760
#define OFF_QL    (OFF_QSC + 200)                // 23960
#define OFF_ISC   (OFF_QL  + 200)                // 24160
#define OFF_IRS   (OFF_ISC + 32)                 // 24192
#define OFF_BJ    (OFF_IRS + 32)                 // 24224
#define RM_FLOATS (OFF_BJ + 32)                  // 24256
#define RM_SMEM   (RM_FLOATS*4)                  // 97024 bytes

__global__ void __launch_bounds__(256) k_relmatch2(
    const float* __restrict__ q_rep, const float* __restrict__ q_last,
    const float* __restrict__ q_mask, const float* __restrict__ d_rep,
    const float* __restrict__ d_mask, float* __restrict__ out)
{
    extern __shared__ float sm[];
    float* dsm    = sm + OFF_DSM;
    float* relsm  = sm + OFF_REL;
    float* wqsm   = sm + OFF_WQ;
    float* qsm    = sm + OFF_QSM;
    float* qscale = sm + OFF_QSC;
    float* qlsm   = sm + OFF_QL;
    float* iscale = sm + OFF_ISC;
    float* irs    = sm + OFF_IRS;
    int*   bjsm   = (int*)(sm + OFF_BJ);

    int b  = blockIdx.x >> 3;
    int it = blockIdx.x & 7;
    int i0g = it * RT;                    // 0,25,...,175
    int tid = threadIdx.x;
    const float* qb = q_rep + (size_t)b*LL*KK;
    const float* db = d_rep + (size_t)b*LL*KK + (size_t)i0g*KK;

    // ---- preamble loads ----
    for (int idx = tid; idx < RT*KK; idx += 256){
        int i = idx / KK, k = idx - i*KK;
        dsm[i*DS_STR + k] = db[idx];
    }
    for (int j = tid; j < LL; j += 256)
        qscale[j] = g_inv_qn[b*LL + j] * q_mask[b*LL + j];
    for (int k = tid; k < KK; k += 256)
        qlsm[k] = q_last[(size_t)b*KK + k];
    if (tid < RT){
        int row = b*LL + i0g + tid;
        iscale[tid] = g_inv_dn[row] * d_mask[row];
    }
    __syncthreads();

    // ---- phase 1: rel GEMM ----
    int ig = tid / 40, jg = tid % 40;     // tid<200: 5 i-groups x 40 j-groups
    float acc[5][5];
    #pragma unroll
    for (int r = 0; r < 5; r++)
        #pragma unroll
        for (int jj = 0; jj < 5; jj++) acc[r][jj] = 0.f;

    for (int k0 = 0; k0 < KK; k0 += RKC){
        for (int idx = tid; idx < RKC*LL; idx += 256){
            int j = idx / RKC, kk = idx - j*RKC;      // coalesced read along k
            qsm[kk*QS_STR + j] = qb[(size_t)j*KK + k0 + kk];
        }
        __syncthreads();
        if (tid < 200){
            #pragma unroll 4
            for (int kk = 0; kk < RKC; kk++){
                float a[5], qv[5];
                #pragma unroll
                for (int r = 0; r < 5; r++)  a[r]  = dsm[(ig*5+r)*DS_STR + k0 + kk];
                #pragma unroll
                for (int jj = 0; jj < 5; jj++) qv[jj] = qsm[kk*QS_STR + jg*5 + jj];
                #pragma unroll
                for (int r = 0; r < 5; r++)
                    #pragma unroll
                    for (int jj = 0; jj < 5; jj++) acc[r][jj] += a[r]*qv[jj];
            }
        }
        __syncthreads();
    }
    if (tid < 200){
        #pragma unroll
        for (int r = 0; r < 5; r++){
            int i = ig*5 + r; float isc = iscale[i];
            #pragma unroll
            for (int jj = 0; jj < 5; jj++){
                int j = jg*5 + jj;
                relsm[i*REL_STR + j] = acc[r][jj] * qscale[j] * isc;
            }
        }
    }
    __syncthreads();

    // ---- phase 2: per-row sum + first-occurrence argmax ----
    {
        int w = tid >> 5, lane = tid & 31;
        for (int i = w; i < RT; i += 8){
            float s = 0.f, bv = -3.402823466e38f; int bi = 0;
            for (int j = lane; j < LL; j += 32){
                float v = relsm[i*REL_STR + j];
                s += v;
                if (v > bv){ bv = v; bi = j; }
            }
            #pragma unroll
            for (int off = 16; off; off >>= 1){
                s += __shfl_xor_sync(0xffffffffu, s, off);
                float ov = __shfl_xor_sync(0xffffffffu, bv, off);
                int   oi = __shfl_xor_sync(0xffffffffu, bi, off);
                if (ov > bv || (ov == bv && oi < bi)){ bv = ov; bi = oi; }
            }
            if (lane == 0){ irs[i] = 1.0f / (s + EPSF); bjsm[i] = bi; }
        }
    }
    __syncthreads();

    // ---- phase 3: wq GEMM (5i x 4k per thread, float4 coalesced q loads) ----
    if (tid < 250){
        int ig2 = tid / 50, kg = tid % 50;
        float a0[5], a1[5], a2[5], a3[5];
        #pragma unroll
        for (int r = 0; r < 5; r++){ a0[r]=0.f; a1[r]=0.f; a2[r]=0.f; a3[r]=0.f; }
        const float4* qb4 = (const float4*)qb;   // 50 float4 per row
        for (int j = 0; j < LL; j++){
            float4 qv = qb4[j*50 + kg];
            #pragma unroll
            for (int r = 0; r < 5; r++){
                float rv = relsm[(ig2*5+r)*REL_STR + j];
                a0[r] += rv*qv.x; a1[r] += rv*qv.y;
                a2[r] += rv*qv.z; a3[r] += rv*qv.w;
            }
        }
        #pragma unroll
        for (int r = 0; r < 5; r++){
            int i = ig2*5 + r; float inv = irs[i];
            float* wp = wqsm + i*WQ_STR + kg*4;
            wp[0] = a0[r]*inv; wp[1] = a1[r]*inv; wp[2] = a2[r]*inv; wp[3] = a3[r]*inv;
        }
    }
    __syncthreads();

    // ---- phase 4: output columns (full / att / max-att) ----
    for (int idx = tid; idx < RT*150; idx += 256){
        int i = idx / 150, o = idx - i*150;
        int grp = o / 50, c = o - grp*50;
        int row = b*LL + i0g + i;
        const float* drow = dsm + i*DS_STR;
        if (grp == 0){
            float s = 0.f;
            #pragma unroll 4
            for (int k = 0; k < KK; k++) s += drow[k]*qlsm[k]*g_fullM2T[k*CC + c];
            out[(size_t)row*OUTC + c] = s * g_inv_fpn[(size_t)row*CC + c]
                                          * g_inv_fqn[b*CC + c];
        } else if (grp == 1){
            const float* wrow = wqsm + i*WQ_STR;
            float sn = 0.f, sq = 0.f;
            #pragma unroll 4
            for (int k = 0; k < KK; k++){
                float m2 = g_attM2T[k*CC + c];
                float wv = wrow[k];
                sn += drow[k]*wv*m2;
                sq += wv*wv*m2;
            }
            out[(size_t)row*OUTC + 150 + c] =
                sn * g_inv_apn[(size_t)row*CC + c] * (1.0f / sqrtf(fmaxf(sq, EPSF)));
        } else {
            int bj = bjsm[i];
            const float* qrow = qb + (size_t)bj*KK;
            float s = 0.f;
            #pragma unroll 4
            for (int k = 0; k < KK; k++) s += drow[k]*qrow[k]*g_xattM2T[k*CC + c];
            out[(size_t)row*OUTC + 200 + c] = s * g_inv_xpn[(size_t)row*CC + c]
                                                * g_inv_xqn[(size_t)(b*LL + bj)*CC + c];
        }
    }
}

// ---------------- kernel 4: maxpool matching (unchanged, ~FFMA floor) ------
#define JC 40
#define TJ 5
#define ASTRIDE 208
#define QSTRIDE 204
#define A_FLOATS (LL*ASTRIDE)
#define Q_FLOATS (JC*QSTRIDE)
#define MP_SMEM ((A_FLOATS + Q_FLOATS)*4)

__global__ void __launch_bounds__(224, 1) k_maxpool(const float* __restrict__ q_rep,
                                                    const float* __restrict__ d_rep,
                                                    float* __restrict__ out)
{
    extern __shared__ float sm[];
    float* Asm = sm;
    float* qsm = sm + A_FLOATS;
    int b = blockIdx.x / CC;
    int c = blockIdx.x - b*CC;
    int tid = threadIdx.x;

    const float* drow = d_rep + (size_t)b*LL*KK;
    const float* m2   = g_mpM2 + (size_t)c*KK;
    for (int idx = tid; idx < LL*KK; idx += 224){
        int i = idx / KK, k = idx - i*KK;
        int phys = i*ASTRIDE + ((((k >> 2) ^ ((i >> 3) & 3)) << 2) | (k & 3));
        Asm[phys] = drow[idx] * m2[k] * g_inv_mpn[(size_t)(b*LL + i)*CC + c];
    }

    int ig = tid >> 3;
    int jg = tid & 7;
    int igx = ig & 3;
    bool act = (ig < 25);
    unsigned mask = __ballot_sync(0xffffffffu, act);

    float rmax[8], rsum[8];
    #pragma unroll
    for (int r = 0; r < 8; r++){ rmax[r] = -3.402823466e38f; rsum[r] = 0.f; }

    const float4* Asm4 = (const float4*)Asm;
    const float4* qsm4 = (const float4*)qsm;
    int abase = ig*8*52;
    int qbase = jg*TJ*51;

    for (int j0 = 0; j0 < LL; j0 += JC){
        __syncthreads();
        for (int idx = tid; idx < JC*KK; idx += 224){
            int j = idx / KK, k = idx - j*KK;
            qsm[j*QSTRIDE + k] = q_rep[((size_t)b*LL + j0 + j)*KK + k]
                               * g_inv_mqn[(size_t)(b*LL + j0 + j)*CC + c];
        }
        __syncthreads();

        if (act){
            float acc[8][TJ];
            #pragma unroll
            for (int r = 0; r < 8; r++)
                #pragma unroll
                for (int jj = 0; jj < TJ; jj++) acc[r][jj] = 0.f;

            #pragma unroll 2
            for (int k4 = 0; k4 < KK/4; k4++){
                float4 qv[TJ];
                #pragma unroll
                for (int jj = 0; jj < TJ; jj++) qv[jj] = qsm4[qbase + jj*51 + k4];
                int ak = k4 ^ igx;
                #pragma unroll
                for (int r = 0; r < 8; r++){
                    float4 av = Asm4[abase + r*52 + ak];
                    #pragma unroll
                    for (int jj = 0; jj < TJ; jj++){
                        acc[r][jj] += av.x * qv[jj].x;
                        acc[r][jj] += av.y * qv[jj].y;
                        acc[r][jj] += av.z * qv[jj].z;
                        acc[r][jj] += av.w * qv[jj].w;
                    }
                }
            }
            #pragma unroll
            for (int r = 0; r < 8; r++){
                float lmax = acc[r][0], lsum = acc[r][0];
                #pragma unroll
                for (int jj = 1; jj < TJ; jj++){
                    lmax = fmaxf(lmax, acc[r][jj]);
                    lsum += acc[r][jj];
                }
                #pragma unroll
                for (int off = 1; off < 8; off <<= 1){
                    lmax = fmaxf(lmax, __shfl_xor_sync(mask, lmax, off));
                    lsum += __shfl_xor_sync(mask, lsum, off);
                }
                rmax[r] = fmaxf(rmax[r], lmax);
                rsum[r] += lsum;
            }
        }
    }

    if (act && jg == 0){
        #pragma unroll
        for (int r = 0; r < 8; r++){
            int i = ig*8 + r;
            float* o = out + ((size_t)b*LL + i)*OUTC;
            o[ 50 + c] = rmax[r];
            o[100 + c] = rsum[r] * (1.0f/200.0f);
        }
    }
}

// ---------------- launcher -------------------------------------------------
extern "C" void kernel_launch(void* const* d_in, const int* in_sizes, int n_in,
                              void* d_out, int out_size)
{
    const float* q_rep  = (const float*)d_in[0];
    const float* q_last = (const float*)d_in[1];
    const float* q_mask = (const float*)d_in[2];
    const float* d_rep  = (const float*)d_in[3];
    // d_in[4] = d_last (unused by reference)
    const float* d_mask = (const float*)d_in[5];
    const float* fullM  = (const float*)d_in[6];
    const float* mpM    = (const float*)d_in[7];
    const float* attM   = (const float*)d_in[8];
    const float* xattM  = (const float*)d_in[9];
    float* out = (float*)d_out;

    k_prep<<<(CC*KK + 255)/256, 256>>>(fullM, mpM, attM, xattM);
    k_norms<<<BB*LL, 512>>>(q_rep, d_rep);
    k_fqn<<<BB, 64>>>(q_last);

    cudaFuncSetAttribute(k_relmatch2, cudaFuncAttributeMaxDynamicSharedMemorySize, RM_SMEM);
    k_relmatch2<<<BB*8, 256, RM_SMEM>>>(q_rep, q_last, q_mask, d_rep, d_mask, out);

    cudaFuncSetAttribute(k_maxpool, cudaFuncAttributeMaxDynamicSharedMemorySize, MP_SMEM);
    k_maxpool<<<BB*CC, 224, MP_SMEM>>>(q_rep, d_rep, out);
}